// round 1
// baseline (speedup 1.0000x reference)
#include <cuda_runtime.h>
#include <cuda_bf16.h>

// Problem dims (fixed by the dataset)
#define BB 4096   // batch
#define DD 1024   // model dim
#define EE 8      // experts
#define CC 4096   // expert output dim
#define KSEL 4    // top-k

// Tiling for the main fused kernel
#define BM 128
#define BN 64
#define BK 16

// gates[b][e] scratch (128 KB device global — allocation-free rule)
__device__ float g_gates[BB * EE];

// ---------------------------------------------------------------------------
// Kernel 1: gating. One warp per row: logits = x[b,:] @ w_gate, top-4 of 8,
// softmax over the selected logits, scatter into g_gates (zeros elsewhere).
// ---------------------------------------------------------------------------
__global__ void gating_kernel(const float* __restrict__ x,
                              const float* __restrict__ wg) {
    int gwarp = (blockIdx.x * blockDim.x + threadIdx.x) >> 5;
    int lane  = threadIdx.x & 31;
    if (gwarp >= BB) return;

    const float* xr = x + (size_t)gwarp * DD;
    float acc[EE];
#pragma unroll
    for (int e = 0; e < EE; e++) acc[e] = 0.f;

    for (int j = lane; j < DD; j += 32) {
        float xv = xr[j];
        const float* wr = wg + (size_t)j * EE;
#pragma unroll
        for (int e = 0; e < EE; e++) acc[e] += xv * wr[e];
    }
#pragma unroll
    for (int off = 16; off; off >>= 1) {
#pragma unroll
        for (int e = 0; e < EE; e++)
            acc[e] += __shfl_xor_sync(0xffffffffu, acc[e], off);
    }

    if (lane == 0) {
        // top-4 selection (strict >, first index wins on ties — matches jax)
        unsigned used = 0;
        float sl[KSEL];
        int   si[KSEL];
#pragma unroll
        for (int t = 0; t < KSEL; t++) {
            float best = -3.0e38f; int bi = 0;
#pragma unroll
            for (int e = 0; e < EE; e++) {
                bool ok = !((used >> e) & 1u);
                if (ok && acc[e] > best) { best = acc[e]; bi = e; }
            }
            used |= 1u << bi;
            sl[t] = best; si[t] = bi;
        }
        // softmax over selected (sl[0] is the max)
        float m = sl[0];
        float ex[KSEL], s = 0.f;
#pragma unroll
        for (int t = 0; t < KSEL; t++) { ex[t] = expf(sl[t] - m); s += ex[t]; }
        float inv = 1.f / s;
        float out[EE];
#pragma unroll
        for (int e = 0; e < EE; e++) out[e] = 0.f;
#pragma unroll
        for (int t = 0; t < KSEL; t++) out[si[t]] = ex[t] * inv;
#pragma unroll
        for (int e = 0; e < EE; e++) g_gates[(size_t)gwarp * EE + e] = out[e];
    }
}

// ---------------------------------------------------------------------------
// Kernel 2: fused expert einsum + exp/combine + log.
// For each (BM x BN) tile: loop e over all 8 experts; per expert run a tiled
// fp32 GEMM over K=1024, then comb += gate[row,e] * exp(acc + b_exp[e,col]).
// Finally y = log(max-ish(comb, eps)).
// ---------------------------------------------------------------------------
__global__ __launch_bounds__(256, 2)
void moe_main(const float* __restrict__ x,
              const float* __restrict__ w_exp,
              const float* __restrict__ b_exp,
              float* __restrict__ y) {
    __shared__ float As[BK][BM];   // x tile, K-major
    __shared__ float Bs[BK][BN];   // w_exp tile
    __shared__ float Gs[BM];       // gates for current expert
    __shared__ float Es[BN];       // b_exp for current expert

    const int tid = threadIdx.x;
    const int bm = blockIdx.y * BM;
    const int bn = blockIdx.x * BN;
    const int ty = tid >> 4;        // 0..15 -> 8 rows each
    const int tx = tid & 15;        // 0..15 -> 4 cols each
    const int row0 = ty * 8;
    const int col0 = tx * 4;

    float comb[8][4];
#pragma unroll
    for (int i = 0; i < 8; i++)
#pragma unroll
        for (int j = 0; j < 4; j++) comb[i][j] = 0.f;

    for (int e = 0; e < EE; e++) {
        // stage per-expert gates / bias (consumed after first __syncthreads)
        if (tid < BM) {
            Gs[tid] = g_gates[(size_t)(bm + tid) * EE + e];
        } else if (tid < BM + BN) {
            Es[tid - BM] = b_exp[(size_t)e * CC + bn + (tid - BM)];
        }

        float acc[8][4];
#pragma unroll
        for (int i = 0; i < 8; i++)
#pragma unroll
            for (int j = 0; j < 4; j++) acc[i][j] = 0.f;

        const float* wbase = w_exp + (size_t)e * DD * CC;

        for (int k0 = 0; k0 < DD; k0 += BK) {
            // load As: 128x16 floats = 512 float4, 2 per thread
#pragma unroll
            for (int i = 0; i < 2; i++) {
                int idx = tid * 2 + i;          // 0..511
                int r   = idx >> 2;             // 0..127
                int kk  = (idx & 3) * 4;        // 0,4,8,12
                float4 v = *(const float4*)(x + (size_t)(bm + r) * DD + k0 + kk);
                As[kk + 0][r] = v.x;
                As[kk + 1][r] = v.y;
                As[kk + 2][r] = v.z;
                As[kk + 3][r] = v.w;
            }
            // load Bs: 16x64 floats, 1 float4 per thread (coalesced)
            {
                int r = tid >> 4;               // 0..15
                int c = (tid & 15) * 4;         // 0..60
                *(float4*)&Bs[r][c] =
                    *(const float4*)(wbase + (size_t)(k0 + r) * CC + bn + c);
            }
            __syncthreads();

#pragma unroll
            for (int kk = 0; kk < BK; kk++) {
                float a[8], b[4];
#pragma unroll
                for (int i = 0; i < 8; i++) a[i] = As[kk][row0 + i];
#pragma unroll
                for (int j = 0; j < 4; j++) b[j] = Bs[kk][col0 + j];
#pragma unroll
                for (int i = 0; i < 8; i++)
#pragma unroll
                    for (int j = 0; j < 4; j++)
                        acc[i][j] = fmaf(a[i], b[j], acc[i][j]);
            }
            __syncthreads();
        }

        // combine: comb += gate * exp(acc + bias)
#pragma unroll
        for (int i = 0; i < 8; i++) {
            float g = Gs[row0 + i];
#pragma unroll
            for (int j = 0; j < 4; j++)
                comb[i][j] += g * __expf(acc[i][j] + Es[col0 + j]);
        }
        __syncthreads();   // protect Gs/Es before next expert overwrites
    }

    // y = log(comb), with comb==0 -> float64 eps
#pragma unroll
    for (int i = 0; i < 8; i++) {
        float out4[4];
#pragma unroll
        for (int j = 0; j < 4; j++) {
            float v = comb[i][j];
            if (v == 0.f) v = 2.2204460492503131e-16f;
            out4[j] = __logf(v);
        }
        *(float4*)(y + (size_t)(bm + row0 + i) * CC + bn + col0) =
            make_float4(out4[0], out4[1], out4[2], out4[3]);
    }
}

// ---------------------------------------------------------------------------
// Kernel 3: balance loss. Deterministic reduction of importance/load over
// g_gates, then cv^2 (ddof=1) for both, written at y[BB*CC].
// ---------------------------------------------------------------------------
__global__ void loss_kernel(float* __restrict__ out) {
    __shared__ float s_imp[8][EE];
    __shared__ float s_load[8][EE];

    int tid  = threadIdx.x;           // 256 threads
    int lane = tid & 31;
    int wid  = tid >> 5;

    float imp[EE], ld[EE];
#pragma unroll
    for (int e = 0; e < EE; e++) { imp[e] = 0.f; ld[e] = 0.f; }

    for (int b = tid; b < BB; b += 256) {
#pragma unroll
        for (int e = 0; e < EE; e++) {
            float g = g_gates[(size_t)b * EE + e];
            imp[e] += g;
            ld[e]  += (g > 0.f) ? 1.f : 0.f;
        }
    }
#pragma unroll
    for (int off = 16; off; off >>= 1) {
#pragma unroll
        for (int e = 0; e < EE; e++) {
            imp[e] += __shfl_xor_sync(0xffffffffu, imp[e], off);
            ld[e]  += __shfl_xor_sync(0xffffffffu, ld[e],  off);
        }
    }
    if (lane == 0) {
#pragma unroll
        for (int e = 0; e < EE; e++) { s_imp[wid][e] = imp[e]; s_load[wid][e] = ld[e]; }
    }
    __syncthreads();

    if (tid == 0) {
        float ti[EE], tl[EE];
#pragma unroll
        for (int e = 0; e < EE; e++) { ti[e] = 0.f; tl[e] = 0.f; }
        for (int w = 0; w < 8; w++) {
#pragma unroll
            for (int e = 0; e < EE; e++) { ti[e] += s_imp[w][e]; tl[e] += s_load[w][e]; }
        }
        // cv_squared with ddof=1
        float mi = 0.f, ml = 0.f;
#pragma unroll
        for (int e = 0; e < EE; e++) { mi += ti[e]; ml += tl[e]; }
        mi /= EE; ml /= EE;
        float vi = 0.f, vl = 0.f;
#pragma unroll
        for (int e = 0; e < EE; e++) {
            float di = ti[e] - mi, dl = tl[e] - ml;
            vi += di * di; vl += dl * dl;
        }
        vi /= (EE - 1); vl /= (EE - 1);
        float cvi = vi / (mi * mi + 1e-10f);
        float cvl = vl / (ml * ml + 1e-10f);
        out[(size_t)BB * CC] = (cvi + cvl) * 0.01f;
    }
}

// ---------------------------------------------------------------------------
extern "C" void kernel_launch(void* const* d_in, const int* in_sizes, int n_in,
                              void* d_out, int out_size) {
    const float* x  = (const float*)d_in[0];
    const float* wg = (const float*)d_in[1];
    const float* we = (const float*)d_in[2];
    const float* be = (const float*)d_in[3];
    float* y = (float*)d_out;

    // gating: 4096 warps
    gating_kernel<<<BB / 4, 128>>>(x, wg);

    // main fused einsum+combine
    dim3 grid(CC / BN, BB / BM);   // (64, 32)
    moe_main<<<grid, 256>>>(x, we, be, y);

    // scalar loss appended after y
    if (out_size > (long long)BB * CC) {
        loss_kernel<<<1, 256>>>(y);
    }
}

// round 5
// speedup vs baseline: 1.9344x; 1.9344x over previous
#include <cuda_runtime.h>
#include <cuda_bf16.h>
#include <cstdint>

// Problem dims (fixed by the dataset)
#define BB 4096   // batch
#define DD 1024   // model dim
#define EE 8      // experts
#define CC 4096   // expert output dim
#define KSEL 4    // top-k

// Main GEMM tiling
#define BM 128
#define BN 64
#define BK 32
#define NCH 96            // 3 segments * (1024/32) k-chunks
#define ASTR 40           // A smem row stride (elems): 80B -> conflict-free ldmatrix
#define BSTR 72           // B smem row stride (elems): 144B -> conflict-free ldmatrix
#define A_STAGE_B (BM * ASTR * 2)   // 10240
#define B_STAGE_B (BK * BSTR * 2)   // 4608

// ---------------------------------------------------------------------------
// Static device scratch (allocation-free rule)
// ---------------------------------------------------------------------------
__device__ float g_gates[BB * EE];
__device__ __align__(16) __nv_bfloat16 g_x_hi[BB * DD];
__device__ __align__(16) __nv_bfloat16 g_x_lo[BB * DD];
__device__ __align__(16) __nv_bfloat16 g_w_hi[(size_t)EE * DD * CC];
__device__ __align__(16) __nv_bfloat16 g_w_lo[(size_t)EE * DD * CC];

__device__ __forceinline__ uint32_t smem_u32(const void* p) {
    uint32_t a;
    asm("{ .reg .u64 t; cvta.to.shared.u64 t, %1; cvt.u32.u64 %0, t; }"
        : "=r"(a) : "l"(p));
    return a;
}

// ---------------------------------------------------------------------------
// Kernel 1: gating. One warp per row: logits, top-4 of 8, softmax, scatter.
// ---------------------------------------------------------------------------
__global__ void gating_kernel(const float* __restrict__ x,
                              const float* __restrict__ wg) {
    int gwarp = (blockIdx.x * blockDim.x + threadIdx.x) >> 5;
    int lane  = threadIdx.x & 31;
    if (gwarp >= BB) return;

    const float* xr = x + (size_t)gwarp * DD;
    float acc[EE];
#pragma unroll
    for (int e = 0; e < EE; e++) acc[e] = 0.f;
    for (int j = lane; j < DD; j += 32) {
        float xv = xr[j];
        const float* wr = wg + (size_t)j * EE;
#pragma unroll
        for (int e = 0; e < EE; e++) acc[e] += xv * wr[e];
    }
#pragma unroll
    for (int off = 16; off; off >>= 1)
#pragma unroll
        for (int e = 0; e < EE; e++)
            acc[e] += __shfl_xor_sync(0xffffffffu, acc[e], off);

    if (lane == 0) {
        unsigned used = 0;
        float sl[KSEL]; int si[KSEL];
#pragma unroll
        for (int t = 0; t < KSEL; t++) {
            float best = -3.0e38f; int bi = 0;
#pragma unroll
            for (int e = 0; e < EE; e++) {
                bool ok = !((used >> e) & 1u);
                if (ok && acc[e] > best) { best = acc[e]; bi = e; }
            }
            used |= 1u << bi; sl[t] = best; si[t] = bi;
        }
        float m = sl[0], ex[KSEL], s = 0.f;
#pragma unroll
        for (int t = 0; t < KSEL; t++) { ex[t] = expf(sl[t] - m); s += ex[t]; }
        float inv = 1.f / s;
        float out[EE];
#pragma unroll
        for (int e = 0; e < EE; e++) out[e] = 0.f;
#pragma unroll
        for (int t = 0; t < KSEL; t++) out[si[t]] = ex[t] * inv;
#pragma unroll
        for (int e = 0; e < EE; e++) g_gates[(size_t)gwarp * EE + e] = out[e];
    }
}

// ---------------------------------------------------------------------------
// Kernel 2/3: elementwise hi/lo bf16 splits (plain row-major layouts)
// ---------------------------------------------------------------------------
__global__ void convert_x(const float* __restrict__ x) {
    int i = blockIdx.x * blockDim.x + threadIdx.x;   // float4 index
    float4 v = ((const float4*)x)[i];
    __nv_bfloat16 h0 = __float2bfloat16(v.x);
    __nv_bfloat16 h1 = __float2bfloat16(v.y);
    __nv_bfloat16 h2 = __float2bfloat16(v.z);
    __nv_bfloat16 h3 = __float2bfloat16(v.w);
    __nv_bfloat162* hp = (__nv_bfloat162*)g_x_hi;
    __nv_bfloat162* lp = (__nv_bfloat162*)g_x_lo;
    hp[2 * i]     = __halves2bfloat162(h0, h1);
    hp[2 * i + 1] = __halves2bfloat162(h2, h3);
    lp[2 * i]     = __halves2bfloat162(
        __float2bfloat16(v.x - __bfloat162float(h0)),
        __float2bfloat16(v.y - __bfloat162float(h1)));
    lp[2 * i + 1] = __halves2bfloat162(
        __float2bfloat16(v.z - __bfloat162float(h2)),
        __float2bfloat16(v.w - __bfloat162float(h3)));
}

__global__ void convert_w(const float* __restrict__ w) {
    size_t i = (size_t)blockIdx.x * blockDim.x + threadIdx.x;  // float4 index
    float4 v = ((const float4*)w)[i];
    __nv_bfloat16 h0 = __float2bfloat16(v.x);
    __nv_bfloat16 h1 = __float2bfloat16(v.y);
    __nv_bfloat16 h2 = __float2bfloat16(v.z);
    __nv_bfloat16 h3 = __float2bfloat16(v.w);
    __nv_bfloat162* hp = (__nv_bfloat162*)g_w_hi;
    __nv_bfloat162* lp = (__nv_bfloat162*)g_w_lo;
    hp[2 * i]     = __halves2bfloat162(h0, h1);
    hp[2 * i + 1] = __halves2bfloat162(h2, h3);
    lp[2 * i]     = __halves2bfloat162(
        __float2bfloat16(v.x - __bfloat162float(h0)),
        __float2bfloat16(v.y - __bfloat162float(h1)));
    lp[2 * i + 1] = __halves2bfloat162(
        __float2bfloat16(v.z - __bfloat162float(h2)),
        __float2bfloat16(v.w - __bfloat162float(h3)));
}

// ---------------------------------------------------------------------------
// Kernel 4: main fused einsum (mma.sync bf16 split-3) + exp/combine + log.
// grid = (BB/BM, CC/BN) = (32, 64), mb fastest for w L2 reuse. 256 threads,
// 8 warps as 4(M) x 2(N); warp tile 32x32; m16n8k16 fragments via ldmatrix.
// ---------------------------------------------------------------------------
__global__ __launch_bounds__(256, 2)
void moe_main(const float* __restrict__ be, float* __restrict__ y) {
    __shared__ __align__(128) __nv_bfloat16 As[2][BM][ASTR];
    __shared__ __align__(128) __nv_bfloat16 Bs[2][BK][BSTR];
    __shared__ float Gs[BM * EE];
    __shared__ float Es[EE * BN];

    const int tid   = threadIdx.x;
    const int lane  = tid & 31;
    const int wid   = tid >> 5;
    const int warpM = wid >> 1;          // 0..3 (32 rows each)
    const int warpN = wid & 1;           // 0..1 (32 cols each)
    const int mb = blockIdx.x;           // 0..31
    const int nb = blockIdx.y;           // 0..63

    for (int i = tid; i < BM * EE; i += 256)
        Gs[i] = g_gates[(size_t)mb * BM * EE + i];
    for (int i = tid; i < EE * BN; i += 256)
        Es[i] = be[(size_t)(i >> 6) * CC + nb * BN + (i & 63)];
    __syncthreads();

    const uint32_t as_base = smem_u32(&As[0][0][0]);
    const uint32_t bs_base = smem_u32(&Bs[0][0][0]);
    const int lm_row = lane & 15;
    const int lm_col = (lane >> 4) << 3;

    // cp.async assignments
    const int a_row0 = tid >> 2;   // + 64 for second chunk
    const int a_ch   = tid & 3;    // 4 x 16B chunks per 32-elem row
    const int b_row  = tid >> 3;
    const int b_ch   = tid & 7;    // 8 x 16B chunks per 64-elem row

    float comb[2][4][4];
#pragma unroll
    for (int mf = 0; mf < 2; mf++)
#pragma unroll
        for (int nf = 0; nf < 4; nf++)
#pragma unroll
            for (int q = 0; q < 4; q++) comb[mf][nf][q] = 0.f;

    for (int e = 0; e < EE; e++) {
        const __nv_bfloat16* whi = g_w_hi + (size_t)e * DD * CC;
        const __nv_bfloat16* wlo = g_w_lo + (size_t)e * DD * CC;

        float acc[2][4][4];
#pragma unroll
        for (int mf = 0; mf < 2; mf++)
#pragma unroll
            for (int nf = 0; nf < 4; nf++)
#pragma unroll
                for (int q = 0; q < 4; q++) acc[mf][nf][q] = 0.f;

        auto issue = [&](int kc, int stg) {
            int seg = kc >> 5;                 // 0: hi*hi, 1: lo*hi, 2: hi*lo
            int kk  = (kc & 31) * BK;
            const __nv_bfloat16* ax = (seg == 1) ? g_x_lo : g_x_hi;
            const __nv_bfloat16* wx = (seg == 2) ? wlo : whi;
            uint32_t adst = as_base + (uint32_t)stg * A_STAGE_B;
            uint32_t bdst = bs_base + (uint32_t)stg * B_STAGE_B;
#pragma unroll
            for (int j = 0; j < 2; j++) {
                int row = a_row0 + j * 64;
                const void* src = ax + (size_t)(mb * BM + row) * DD + kk + a_ch * 8;
                uint32_t dst = adst + (uint32_t)(row * ASTR + a_ch * 8) * 2;
                asm volatile("cp.async.cg.shared.global [%0], [%1], 16;"
                             :: "r"(dst), "l"(src));
            }
            {
                const void* src = wx + (size_t)(kk + b_row) * CC + nb * BN + b_ch * 8;
                uint32_t dst = bdst + (uint32_t)(b_row * BSTR + b_ch * 8) * 2;
                asm volatile("cp.async.cg.shared.global [%0], [%1], 16;"
                             :: "r"(dst), "l"(src));
            }
            asm volatile("cp.async.commit_group;");
        };

        auto compute = [&](int stg) {
#pragma unroll
            for (int ks = 0; ks < 2; ks++) {
                uint32_t a[2][4], b[4][2];
#pragma unroll
                for (int mf = 0; mf < 2; mf++) {
                    uint32_t addr = as_base + (uint32_t)stg * A_STAGE_B +
                        (uint32_t)((warpM * 32 + mf * 16 + lm_row) * ASTR +
                                   ks * 16 + lm_col) * 2;
                    asm volatile(
                        "ldmatrix.sync.aligned.m8n8.x4.shared.b16 {%0,%1,%2,%3}, [%4];"
                        : "=r"(a[mf][0]), "=r"(a[mf][1]), "=r"(a[mf][2]), "=r"(a[mf][3])
                        : "r"(addr));
                }
#pragma unroll
                for (int np = 0; np < 2; np++) {
                    uint32_t addr = bs_base + (uint32_t)stg * B_STAGE_B +
                        (uint32_t)((ks * 16 + lm_row) * BSTR +
                                   warpN * 32 + np * 16 + lm_col) * 2;
                    uint32_t t0, t1, t2, t3;
                    asm volatile(
                        "ldmatrix.sync.aligned.m8n8.x4.trans.shared.b16 {%0,%1,%2,%3}, [%4];"
                        : "=r"(t0), "=r"(t1), "=r"(t2), "=r"(t3) : "r"(addr));
                    b[np * 2][0] = t0;     b[np * 2][1] = t1;
                    b[np * 2 + 1][0] = t2; b[np * 2 + 1][1] = t3;
                }
#pragma unroll
                for (int mf = 0; mf < 2; mf++)
#pragma unroll
                    for (int nf = 0; nf < 4; nf++)
                        asm volatile(
                            "mma.sync.aligned.m16n8k16.row.col.f32.bf16.bf16.f32 "
                            "{%0,%1,%2,%3}, {%4,%5,%6,%7}, {%8,%9}, {%0,%1,%2,%3};"
                            : "+f"(acc[mf][nf][0]), "+f"(acc[mf][nf][1]),
                              "+f"(acc[mf][nf][2]), "+f"(acc[mf][nf][3])
                            : "r"(a[mf][0]), "r"(a[mf][1]),
                              "r"(a[mf][2]), "r"(a[mf][3]),
                              "r"(b[nf][0]), "r"(b[nf][1]));
            }
        };

        issue(0, 0);
        for (int kc = 0; kc < NCH; kc++) {
            if (kc + 1 < NCH) {
                issue(kc + 1, (kc + 1) & 1);
                asm volatile("cp.async.wait_group 1;" ::: "memory");
            } else {
                asm volatile("cp.async.wait_group 0;" ::: "memory");
            }
            __syncthreads();
            compute(kc & 1);
            __syncthreads();
        }

        // combine this expert: comb += gate * exp(acc + bias)
        const int r0 = warpM * 32 + (lane >> 2);
        const int c0 = warpN * 32 + (lane & 3) * 2;
#pragma unroll
        for (int mf = 0; mf < 2; mf++) {
            float gA = Gs[(r0 + mf * 16) * EE + e];
            float gB = Gs[(r0 + mf * 16 + 8) * EE + e];
#pragma unroll
            for (int nf = 0; nf < 4; nf++) {
                int c = c0 + nf * 8;
                float b0 = Es[e * BN + c], b1 = Es[e * BN + c + 1];
                comb[mf][nf][0] += gA * __expf(acc[mf][nf][0] + b0);
                comb[mf][nf][1] += gA * __expf(acc[mf][nf][1] + b1);
                comb[mf][nf][2] += gB * __expf(acc[mf][nf][2] + b0);
                comb[mf][nf][3] += gB * __expf(acc[mf][nf][3] + b1);
            }
        }
    }

    // y = log(comb) with comb==0 -> float64 eps
    const int r0 = warpM * 32 + (lane >> 2);
    const int c0 = warpN * 32 + (lane & 3) * 2;
#pragma unroll
    for (int mf = 0; mf < 2; mf++)
#pragma unroll
        for (int q = 0; q < 2; q++) {
            int row = mb * BM + r0 + mf * 16 + q * 8;
#pragma unroll
            for (int nf = 0; nf < 4; nf++) {
                int c = nb * BN + c0 + nf * 8;
                float v0 = comb[mf][nf][q * 2 + 0];
                float v1 = comb[mf][nf][q * 2 + 1];
                if (v0 == 0.f) v0 = 2.2204460492503131e-16f;
                if (v1 == 0.f) v1 = 2.2204460492503131e-16f;
                *(float2*)(y + (size_t)row * CC + c) =
                    make_float2(__logf(v0), __logf(v1));
            }
        }
}

// ---------------------------------------------------------------------------
// Kernel 5: balance loss
// ---------------------------------------------------------------------------
__global__ void loss_kernel(float* __restrict__ out) {
    __shared__ float s_imp[8][EE];
    __shared__ float s_load[8][EE];
    int tid = threadIdx.x, lane = tid & 31, wid = tid >> 5;
    float imp[EE], ld[EE];
#pragma unroll
    for (int e = 0; e < EE; e++) { imp[e] = 0.f; ld[e] = 0.f; }
    for (int b = tid; b < BB; b += 256) {
#pragma unroll
        for (int e = 0; e < EE; e++) {
            float g = g_gates[(size_t)b * EE + e];
            imp[e] += g;
            ld[e]  += (g > 0.f) ? 1.f : 0.f;
        }
    }
#pragma unroll
    for (int off = 16; off; off >>= 1)
#pragma unroll
        for (int e = 0; e < EE; e++) {
            imp[e] += __shfl_xor_sync(0xffffffffu, imp[e], off);
            ld[e]  += __shfl_xor_sync(0xffffffffu, ld[e],  off);
        }
    if (lane == 0)
#pragma unroll
        for (int e = 0; e < EE; e++) { s_imp[wid][e] = imp[e]; s_load[wid][e] = ld[e]; }
    __syncthreads();
    if (tid == 0) {
        float ti[EE], tl[EE];
#pragma unroll
        for (int e = 0; e < EE; e++) { ti[e] = 0.f; tl[e] = 0.f; }
        for (int w = 0; w < 8; w++)
#pragma unroll
            for (int e = 0; e < EE; e++) { ti[e] += s_imp[w][e]; tl[e] += s_load[w][e]; }
        float mi = 0.f, ml = 0.f;
#pragma unroll
        for (int e = 0; e < EE; e++) { mi += ti[e]; ml += tl[e]; }
        mi /= EE; ml /= EE;
        float vi = 0.f, vl = 0.f;
#pragma unroll
        for (int e = 0; e < EE; e++) {
            float di = ti[e] - mi, dl = tl[e] - ml;
            vi += di * di; vl += dl * dl;
        }
        vi /= (EE - 1); vl /= (EE - 1);
        out[(size_t)BB * CC] =
            (vi / (mi * mi + 1e-10f) + vl / (ml * ml + 1e-10f)) * 0.01f;
    }
}

// ---------------------------------------------------------------------------
extern "C" void kernel_launch(void* const* d_in, const int* in_sizes, int n_in,
                              void* d_out, int out_size) {
    const float* x  = (const float*)d_in[0];
    const float* wg = (const float*)d_in[1];
    const float* we = (const float*)d_in[2];
    const float* be = (const float*)d_in[3];
    float* y = (float*)d_out;

    gating_kernel<<<BB / 4, 128>>>(x, wg);
    convert_x<<<(BB * DD / 4) / 256, 256>>>(x);                      // 4096 blocks
    convert_w<<<(int)(((size_t)EE * DD * CC / 4) / 256), 256>>>(we); // 32768 blocks

    dim3 grid(BB / BM, CC / BN);   // (32, 64): mb fastest -> w reuse in L2
    moe_main<<<grid, 256>>>(be, y);

    if (out_size > (long long)BB * CC) loss_kernel<<<1, 256>>>(y);
}

// round 6
// speedup vs baseline: 4.3232x; 2.2349x over previous
#include <cuda_runtime.h>
#include <cuda_bf16.h>
#include <cstdint>

// Problem dims (fixed by the dataset)
#define BB 4096   // batch
#define DD 1024   // model dim
#define EE 8      // experts
#define CC 4096   // expert output dim
#define KSEL 4    // top-k

// Main GEMM tiling
#define BM 128
#define BN 64
#define BK 64
#define NCH 48            // 3 segments * (1024/64) k-chunks
#define NSTG 3            // pipeline stages
#define STR 72            // smem row stride (elems): 144B -> conflict-free ldmatrix
#define A_ST_B (BM * STR * 2)            // 18432
#define B_ST_B (BK * STR * 2)            // 9216
#define STAGE_B (A_ST_B + B_ST_B)        // 27648
#define SMEM_DYN (NSTG * STAGE_B)        // 82944
#define MAXT 136                          // max M-tiles: ceil(16384/128)+7, padded

// ---------------------------------------------------------------------------
// Static device scratch (allocation-free rule)
// ---------------------------------------------------------------------------
__device__ float g_gates[BB * EE];
__device__ int   g_cnt[EE];
__device__ int   g_list[EE * BB];          // per-expert row lists (padded with -1)
__device__ int4  g_rowslot[BB];            // per row: 4x ((e<<16)|slot), selection order
__device__ int   g_map_e[MAXT];
__device__ int   g_map_lb[MAXT];           // list-index base for tile
__device__ int   g_pbase[EE];              // padded global slot base per expert
__device__ __align__(16) __nv_bfloat16 g_x_hi[BB * DD];
__device__ __align__(16) __nv_bfloat16 g_x_lo[BB * DD];
__device__ __align__(16) __nv_bfloat16 g_w_hi[(size_t)EE * DD * CC];
__device__ __align__(16) __nv_bfloat16 g_w_lo[(size_t)EE * DD * CC];
__device__ __align__(16) float g_eo[(size_t)MAXT * BM * CC];  // per-(slot,col) contrib

__device__ __forceinline__ uint32_t smem_u32(const void* p) {
    uint32_t a;
    asm("{ .reg .u64 t; cvta.to.shared.u64 t, %1; cvt.u32.u64 %0, t; }"
        : "=r"(a) : "l"(p));
    return a;
}

// ---------------------------------------------------------------------------
// Kernel 0: zero counters
// ---------------------------------------------------------------------------
__global__ void zero_cnt() { if (threadIdx.x < EE) g_cnt[threadIdx.x] = 0; }

// ---------------------------------------------------------------------------
// Kernel 1: gating. One warp per row: logits, top-4 of 8, softmax, scatter,
// and per-expert list building (slot via atomicAdd; values order-independent).
// ---------------------------------------------------------------------------
__global__ void gating_kernel(const float* __restrict__ x,
                              const float* __restrict__ wg) {
    int row  = (blockIdx.x * blockDim.x + threadIdx.x) >> 5;
    int lane = threadIdx.x & 31;
    if (row >= BB) return;

    const float* xr = x + (size_t)row * DD;
    float acc[EE];
#pragma unroll
    for (int e = 0; e < EE; e++) acc[e] = 0.f;
    for (int j = lane; j < DD; j += 32) {
        float xv = xr[j];
        const float* wr = wg + (size_t)j * EE;
#pragma unroll
        for (int e = 0; e < EE; e++) acc[e] += xv * wr[e];
    }
#pragma unroll
    for (int off = 16; off; off >>= 1)
#pragma unroll
        for (int e = 0; e < EE; e++)
            acc[e] += __shfl_xor_sync(0xffffffffu, acc[e], off);

    if (lane == 0) {
        unsigned used = 0;
        float sl[KSEL]; int si[KSEL];
#pragma unroll
        for (int t = 0; t < KSEL; t++) {
            float best = -3.0e38f; int bi = 0;
#pragma unroll
            for (int e = 0; e < EE; e++) {
                bool ok = !((used >> e) & 1u);
                if (ok && acc[e] > best) { best = acc[e]; bi = e; }
            }
            used |= 1u << bi; sl[t] = best; si[t] = bi;
        }
        float m = sl[0], ex[KSEL], s = 0.f;
#pragma unroll
        for (int t = 0; t < KSEL; t++) { ex[t] = expf(sl[t] - m); s += ex[t]; }
        float inv = 1.f / s;
        float out[EE];
#pragma unroll
        for (int e = 0; e < EE; e++) out[e] = 0.f;
#pragma unroll
        for (int t = 0; t < KSEL; t++) out[si[t]] = ex[t] * inv;
#pragma unroll
        for (int e = 0; e < EE; e++) g_gates[(size_t)row * EE + e] = out[e];

        int pk[KSEL];
#pragma unroll
        for (int t = 0; t < KSEL; t++) {
            int slot = atomicAdd(&g_cnt[si[t]], 1);
            g_list[si[t] * BB + slot] = row;
            pk[t] = (si[t] << 16) | slot;
        }
        g_rowslot[row] = make_int4(pk[0], pk[1], pk[2], pk[3]);
    }
}

// ---------------------------------------------------------------------------
// Kernel 2: build tile map (serial, trivial work)
// ---------------------------------------------------------------------------
__global__ void map_kernel() {
    if (threadIdx.x != 0 || blockIdx.x != 0) return;
    int t = 0;
    for (int e = 0; e < EE; e++) {
        int c  = g_cnt[e];
        int nt = (c + BM - 1) >> 7;
        g_pbase[e] = t * BM;
        for (int i = 0; i < nt; i++) {
            g_map_e[t]  = e;
            g_map_lb[t] = e * BB + i * BM;
            t++;
        }
        for (int s = c; s < nt * BM; s++) g_list[e * BB + s] = -1;
    }
    for (; t < MAXT; t++) g_map_e[t] = -1;
}

// ---------------------------------------------------------------------------
// Kernel 3/4: elementwise hi/lo bf16 splits
// ---------------------------------------------------------------------------
__global__ void convert_x(const float* __restrict__ x) {
    int i = blockIdx.x * blockDim.x + threadIdx.x;
    float4 v = ((const float4*)x)[i];
    __nv_bfloat16 h0 = __float2bfloat16(v.x), h1 = __float2bfloat16(v.y);
    __nv_bfloat16 h2 = __float2bfloat16(v.z), h3 = __float2bfloat16(v.w);
    __nv_bfloat162* hp = (__nv_bfloat162*)g_x_hi;
    __nv_bfloat162* lp = (__nv_bfloat162*)g_x_lo;
    hp[2 * i]     = __halves2bfloat162(h0, h1);
    hp[2 * i + 1] = __halves2bfloat162(h2, h3);
    lp[2 * i]     = __halves2bfloat162(
        __float2bfloat16(v.x - __bfloat162float(h0)),
        __float2bfloat16(v.y - __bfloat162float(h1)));
    lp[2 * i + 1] = __halves2bfloat162(
        __float2bfloat16(v.z - __bfloat162float(h2)),
        __float2bfloat16(v.w - __bfloat162float(h3)));
}

__global__ void convert_w(const float* __restrict__ w) {
    size_t i = (size_t)blockIdx.x * blockDim.x + threadIdx.x;
    float4 v = ((const float4*)w)[i];
    __nv_bfloat16 h0 = __float2bfloat16(v.x), h1 = __float2bfloat16(v.y);
    __nv_bfloat16 h2 = __float2bfloat16(v.z), h3 = __float2bfloat16(v.w);
    __nv_bfloat162* hp = (__nv_bfloat162*)g_w_hi;
    __nv_bfloat162* lp = (__nv_bfloat162*)g_w_lo;
    hp[2 * i]     = __halves2bfloat162(h0, h1);
    hp[2 * i + 1] = __halves2bfloat162(h2, h3);
    lp[2 * i]     = __halves2bfloat162(
        __float2bfloat16(v.x - __bfloat162float(h0)),
        __float2bfloat16(v.y - __bfloat162float(h1)));
    lp[2 * i + 1] = __halves2bfloat162(
        __float2bfloat16(v.z - __bfloat162float(h2)),
        __float2bfloat16(v.w - __bfloat162float(h3)));
}

// ---------------------------------------------------------------------------
// Kernel 5: sparse expert GEMM (mma.sync bf16 split-3), 3-stage pipeline.
// grid = (MAXT, CC/BN). One expert per CTA; rows gathered from g_list.
// Epilogue: g_eo[slot][col] = gate * exp(acc + bias)   (streaming store)
// ---------------------------------------------------------------------------
__global__ __launch_bounds__(256, 2)
void moe_main(const float* __restrict__ be) {
    const int t = blockIdx.x;
    const int e = g_map_e[t];
    if (e < 0) return;
    const int nb = blockIdx.y;

    extern __shared__ __align__(128) char sdyn[];
    __shared__ int   rl[BM];
    __shared__ float Gs[BM];
    __shared__ float Es[BN];

    const int tid   = threadIdx.x;
    const int lane  = tid & 31;
    const int wid   = tid >> 5;
    const int warpM = wid >> 1;          // 0..3 (32 rows each)
    const int warpN = wid & 1;           // 0..1 (32 cols each)

    if (tid < BM) {
        int r = g_list[g_map_lb[t] + tid];
        rl[tid] = (r < 0) ? 0 : r;
        Gs[tid] = (r < 0) ? 0.f : g_gates[(size_t)r * EE + e];
    } else if (tid < BM + BN) {
        Es[tid - BM] = be[(size_t)e * CC + nb * BN + (tid - BM)];
    }
    __syncthreads();

    const uint32_t sb = smem_u32(sdyn);

    // per-thread constant offsets
    size_t rowoff[4];
#pragma unroll
    for (int i = 0; i < 4; i++)
        rowoff[i] = (size_t)rl[(tid >> 3) + 32 * i] * DD;
    const int a_ch = (tid & 7) * 8;          // element offset of 16B chunk
    uint32_t dstA[4];
#pragma unroll
    for (int i = 0; i < 4; i++)
        dstA[i] = (uint32_t)((((tid >> 3) + 32 * i) * STR + a_ch) * 2);
    const int b_row0 = tid >> 3;             // +32 for i=1
    uint32_t dstB[2];
#pragma unroll
    for (int i = 0; i < 2; i++)
        dstB[i] = (uint32_t)(((b_row0 + 32 * i) * STR + a_ch) * 2);

    const __nv_bfloat16* whi = g_w_hi + (size_t)e * DD * CC;
    const __nv_bfloat16* wlo = g_w_lo + (size_t)e * DD * CC;

    auto issue = [&](int kc) {
        int stg = kc % NSTG;
        int seg = kc >> 4;                    // 16 chunks per segment
        int kk  = (kc & 15) * BK;
        const __nv_bfloat16* ax = (seg == 1) ? g_x_lo : g_x_hi;
        const __nv_bfloat16* wx = (seg == 2) ? wlo : whi;
        uint32_t ab = sb + stg * STAGE_B;
        uint32_t bb = ab + A_ST_B;
#pragma unroll
        for (int i = 0; i < 4; i++) {
            const void* src = ax + rowoff[i] + kk + a_ch;
            asm volatile("cp.async.cg.shared.global [%0], [%1], 16;"
                         :: "r"(ab + dstA[i]), "l"(src));
        }
#pragma unroll
        for (int i = 0; i < 2; i++) {
            const void* src = wx + (size_t)(kk + b_row0 + 32 * i) * CC
                              + nb * BN + a_ch;
            asm volatile("cp.async.cg.shared.global [%0], [%1], 16;"
                         :: "r"(bb + dstB[i]), "l"(src));
        }
        asm volatile("cp.async.commit_group;");
    };

    float acc[2][4][4];
#pragma unroll
    for (int mf = 0; mf < 2; mf++)
#pragma unroll
        for (int nf = 0; nf < 4; nf++)
#pragma unroll
            for (int q = 0; q < 4; q++) acc[mf][nf][q] = 0.f;

    const int lm_row = lane & 15;
    const int lm_col = (lane >> 4) << 3;

    issue(0);
    issue(1);

    for (int c = 0; c < NCH; c++) {
        if (c < NCH - 1)
            asm volatile("cp.async.wait_group 1;" ::: "memory");
        else
            asm volatile("cp.async.wait_group 0;" ::: "memory");
        __syncthreads();
        if (c + 2 < NCH) issue(c + 2);

        int stg = c % NSTG;
        uint32_t ab = sb + stg * STAGE_B;
        uint32_t bb = ab + A_ST_B;
#pragma unroll
        for (int ks = 0; ks < 4; ks++) {
            uint32_t a[2][4], b[4][2];
#pragma unroll
            for (int mf = 0; mf < 2; mf++) {
                uint32_t addr = ab +
                    (uint32_t)(((warpM * 32 + mf * 16 + lm_row) * STR +
                                ks * 16 + lm_col) * 2);
                asm volatile(
                    "ldmatrix.sync.aligned.m8n8.x4.shared.b16 {%0,%1,%2,%3}, [%4];"
                    : "=r"(a[mf][0]), "=r"(a[mf][1]), "=r"(a[mf][2]), "=r"(a[mf][3])
                    : "r"(addr));
            }
#pragma unroll
            for (int np = 0; np < 2; np++) {
                uint32_t addr = bb +
                    (uint32_t)(((ks * 16 + lm_row) * STR +
                                warpN * 32 + np * 16 + lm_col) * 2);
                uint32_t t0, t1, t2, t3;
                asm volatile(
                    "ldmatrix.sync.aligned.m8n8.x4.trans.shared.b16 {%0,%1,%2,%3}, [%4];"
                    : "=r"(t0), "=r"(t1), "=r"(t2), "=r"(t3) : "r"(addr));
                b[np * 2][0] = t0;     b[np * 2][1] = t1;
                b[np * 2 + 1][0] = t2; b[np * 2 + 1][1] = t3;
            }
#pragma unroll
            for (int mf = 0; mf < 2; mf++)
#pragma unroll
                for (int nf = 0; nf < 4; nf++)
                    asm volatile(
                        "mma.sync.aligned.m16n8k16.row.col.f32.bf16.bf16.f32 "
                        "{%0,%1,%2,%3}, {%4,%5,%6,%7}, {%8,%9}, {%0,%1,%2,%3};"
                        : "+f"(acc[mf][nf][0]), "+f"(acc[mf][nf][1]),
                          "+f"(acc[mf][nf][2]), "+f"(acc[mf][nf][3])
                        : "r"(a[mf][0]), "r"(a[mf][1]),
                          "r"(a[mf][2]), "r"(a[mf][3]),
                          "r"(b[nf][0]), "r"(b[nf][1]));
        }
    }

    // epilogue: g_eo[t*BM + local_row][nb*BN + col] = g * exp(acc + bias)
    const int r0 = warpM * 32 + (lane >> 2);
    const int c0 = warpN * 32 + (lane & 3) * 2;
    float* ob = g_eo + ((size_t)t * BM) * CC + (size_t)nb * BN;
#pragma unroll
    for (int mf = 0; mf < 2; mf++)
#pragma unroll
        for (int q = 0; q < 2; q++) {
            int rr = r0 + mf * 16 + q * 8;
            float g = Gs[rr];
#pragma unroll
            for (int nf = 0; nf < 4; nf++) {
                int cc = c0 + nf * 8;
                float v0 = g * __expf(acc[mf][nf][q * 2 + 0] + Es[cc]);
                float v1 = g * __expf(acc[mf][nf][q * 2 + 1] + Es[cc + 1]);
                *(float2*)(ob + (size_t)rr * CC + cc) = make_float2(v0, v1);
            }
        }
}

// ---------------------------------------------------------------------------
// Kernel 6: final combine. Each block = one row; sum the row's 4 fixed-order
// expert contributions (coalesced streams), eps guard, log.
// ---------------------------------------------------------------------------
__global__ void final_kernel(float* __restrict__ y) {
    int row = blockIdx.x;
    int4 rs = g_rowslot[row];
    const float* p0 = g_eo + (size_t)(g_pbase[rs.x >> 16] + (rs.x & 0xFFFF)) * CC;
    const float* p1 = g_eo + (size_t)(g_pbase[rs.y >> 16] + (rs.y & 0xFFFF)) * CC;
    const float* p2 = g_eo + (size_t)(g_pbase[rs.z >> 16] + (rs.z & 0xFFFF)) * CC;
    const float* p3 = g_eo + (size_t)(g_pbase[rs.w >> 16] + (rs.w & 0xFFFF)) * CC;
    float4* yo = (float4*)(y + (size_t)row * CC);
#pragma unroll
    for (int i = 0; i < 4; i++) {
        int c = threadIdx.x + i * 256;
        float4 a = ((const float4*)p0)[c];
        float4 b = ((const float4*)p1)[c];
        float4 d = ((const float4*)p2)[c];
        float4 f = ((const float4*)p3)[c];
        float s0 = a.x + b.x + d.x + f.x;
        float s1 = a.y + b.y + d.y + f.y;
        float s2 = a.z + b.z + d.z + f.z;
        float s3 = a.w + b.w + d.w + f.w;
        if (s0 == 0.f) s0 = 2.2204460492503131e-16f;
        if (s1 == 0.f) s1 = 2.2204460492503131e-16f;
        if (s2 == 0.f) s2 = 2.2204460492503131e-16f;
        if (s3 == 0.f) s3 = 2.2204460492503131e-16f;
        yo[c] = make_float4(__logf(s0), __logf(s1), __logf(s2), __logf(s3));
    }
}

// ---------------------------------------------------------------------------
// Kernel 7: balance loss
// ---------------------------------------------------------------------------
__global__ void loss_kernel(float* __restrict__ out) {
    __shared__ float s_imp[8][EE];
    __shared__ float s_load[8][EE];
    int tid = threadIdx.x, lane = tid & 31, wid = tid >> 5;
    float imp[EE], ld[EE];
#pragma unroll
    for (int e = 0; e < EE; e++) { imp[e] = 0.f; ld[e] = 0.f; }
    for (int b = tid; b < BB; b += 256) {
#pragma unroll
        for (int e = 0; e < EE; e++) {
            float g = g_gates[(size_t)b * EE + e];
            imp[e] += g;
            ld[e]  += (g > 0.f) ? 1.f : 0.f;
        }
    }
#pragma unroll
    for (int off = 16; off; off >>= 1)
#pragma unroll
        for (int e = 0; e < EE; e++) {
            imp[e] += __shfl_xor_sync(0xffffffffu, imp[e], off);
            ld[e]  += __shfl_xor_sync(0xffffffffu, ld[e],  off);
        }
    if (lane == 0)
#pragma unroll
        for (int e = 0; e < EE; e++) { s_imp[wid][e] = imp[e]; s_load[wid][e] = ld[e]; }
    __syncthreads();
    if (tid == 0) {
        float ti[EE], tl[EE];
#pragma unroll
        for (int e = 0; e < EE; e++) { ti[e] = 0.f; tl[e] = 0.f; }
        for (int w = 0; w < 8; w++)
#pragma unroll
            for (int e = 0; e < EE; e++) { ti[e] += s_imp[w][e]; tl[e] += s_load[w][e]; }
        float mi = 0.f, ml = 0.f;
#pragma unroll
        for (int e = 0; e < EE; e++) { mi += ti[e]; ml += tl[e]; }
        mi /= EE; ml /= EE;
        float vi = 0.f, vl = 0.f;
#pragma unroll
        for (int e = 0; e < EE; e++) {
            float di = ti[e] - mi, dl = tl[e] - ml;
            vi += di * di; vl += dl * dl;
        }
        vi /= (EE - 1); vl /= (EE - 1);
        out[(size_t)BB * CC] =
            (vi / (mi * mi + 1e-10f) + vl / (ml * ml + 1e-10f)) * 0.01f;
    }
}

// ---------------------------------------------------------------------------
extern "C" void kernel_launch(void* const* d_in, const int* in_sizes, int n_in,
                              void* d_out, int out_size) {
    const float* x  = (const float*)d_in[0];
    const float* wg = (const float*)d_in[1];
    const float* we = (const float*)d_in[2];
    const float* be = (const float*)d_in[3];
    float* y = (float*)d_out;

    cudaFuncSetAttribute(moe_main, cudaFuncAttributeMaxDynamicSharedMemorySize,
                         SMEM_DYN);

    zero_cnt<<<1, 32>>>();
    gating_kernel<<<BB / 4, 128>>>(x, wg);
    map_kernel<<<1, 32>>>();
    convert_x<<<(BB * DD / 4) / 256, 256>>>(x);
    convert_w<<<(int)(((size_t)EE * DD * CC / 4) / 256), 256>>>(we);

    dim3 grid(MAXT, CC / BN);   // (136, 64)
    moe_main<<<grid, 256, SMEM_DYN>>>(be);

    final_kernel<<<BB, 256>>>(y);
    if (out_size > (long long)BB * CC) loss_kernel<<<1, 256>>>(y);
}